// round 6
// baseline (speedup 1.0000x reference)
#include <cuda_runtime.h>
#include <cuda_bf16.h>
#include <math.h>
#include <stdint.h>
#include <string.h>

// Problem constants
#define BATCH 32
#define CIN   8
#define COUT  8
#define KP    4
#define DIN   16
#define DOUT  16
#define SS_   32
#define EPSV  1e-5f

#define NPTS  (BATCH*SS_*SS_)      // 32768 spatial points (b,y,x)
#define NOC   (CIN*COUT*DOUT)      // 1024 conv output channels
#define KDIM  (DIN*9)              // 144 GEMM K (fp32)
#define KEFF  432                  // 3*144 split-bf16 K
#define KPAD  448                  // padded: 14 stages of BK=32
#define OD    (COUT*DOUT)          // 128 (o,d) pairs per point

typedef unsigned long long u64;

// ---------------- packed f32x2 helpers ------------------------------------
__device__ __forceinline__ u64 pack2(float lo, float hi) {
    u64 d; asm("mov.b64 %0,{%1,%2};" : "=l"(d) : "f"(lo), "f"(hi)); return d;
}
__device__ __forceinline__ u64 ffma2(u64 a, u64 b, u64 c) {
    u64 d; asm("fma.rn.f32x2 %0,%1,%2,%3;" : "=l"(d) : "l"(a), "l"(b), "l"(c)); return d;
}
__device__ __forceinline__ u64 fadd2(u64 a, u64 b) {
    u64 d; asm("add.rn.f32x2 %0,%1,%2;" : "=l"(d) : "l"(a), "l"(b)); return d;
}
__device__ __forceinline__ void unpack2(u64 d, float& lo, float& hi) {
    asm("mov.b64 {%0,%1},%2;" : "=f"(lo), "=f"(hi) : "l"(d));
}

__device__ __forceinline__ uint32_t smem_u32(const void* p) {
    uint32_t a;
    asm("{ .reg .u64 t; cvta.to.shared.u64 t, %1; cvt.u32.u64 %0, t; }" : "=r"(a) : "l"(p));
    return a;
}
#define CP_ASYNC16(dst, src) asm volatile("cp.async.cg.shared.global [%0], [%1], 16;" :: "r"(dst), "l"(src))
#define CP_COMMIT()          asm volatile("cp.async.commit_group;" ::: "memory")

// ---------------- scratch (device globals) --------------------------------
__device__ __align__(128) __nv_bfloat16 g_Ab[NPTS*KPAD];   // split-bf16 im2col A [p][e]
__device__ __align__(128) __nv_bfloat16 g_Bb[NOC*KPAD];    // split-bf16 weights [oc][e]
__device__ __align__(128) float g_votes[NPTS*NOC];         // conv output [pt][oc]
__device__ __align__(128) float g_sumAtt[NPTS*OD];
__device__ __align__(128) float g_pmax[NPTS*OD];
__device__ __align__(128) float g_pmean[NPTS*OD];
__device__ __align__(128) float g_gate[NPTS*OD];
__device__ float g_psumArr[4096*8];
__device__ float g_pssArr[4096*8];
__device__ float g_bnMu[8];
__device__ float g_bnRstd[8];

// ---------------- kernel: prep B (split Wt -> bf16 [oc][448]) -------------
// A terms: [hi, hi, lo]; B terms: [hi, lo, hi]  => hi*hi + hi*lo + lo*hi
__global__ void k_prepB(const float* __restrict__ Wt) {
    int idx = blockIdx.x * 256 + threadIdx.x;   // 1792 blocks exact
    int oc = idx / KPAD, e = idx % KPAD;
    float v = 0.f;
    if (e < KEFF) {
        int t = e / KDIM, k = e - t*KDIM;
        float w = Wt[oc*KDIM + k];
        float hi = __bfloat162float(__float2bfloat16_rn(w));
        v = (t == 1) ? (w - hi) : hi;
    }
    g_Bb[idx] = __float2bfloat16_rn(v);
}

// ---------------- kernel: prep A (im2col + split -> bf16 [p][448]) --------
// block = 64 points (2 y-rows of one image). grid 512.
__global__ __launch_bounds__(256) void k_prepA(const float* __restrict__ caps) {
    extern __shared__ char sm[];
    float* raw = (float*)sm;                       // 16 din x 4 rows x 32 = 2048 f
    uint32_t* outp = (uint32_t*)(sm + 8192);       // [64][225] u32 (padded stride)
    int tid = threadIdx.x;
    int m064 = blockIdx.x * 64;
    int b = m064 >> 10;
    int y0 = (m064 & 1023) >> 5;
    for (int i = tid; i < 2048; i += 256) {
        int din = i >> 7, rem = i & 127, yy = y0 - 1 + (rem >> 5), x = rem & 31;
        raw[i] = ((unsigned)yy < 32u) ? caps[b*16384 + din*1024 + yy*32 + x] : 0.f;
    }
    __syncthreads();
    int p = tid & 63, part = tid >> 6;
    int y_local = p >> 5, x = p & 31;
    bool isLo = part >= 2;
    int j0 = (part & 1) * 36;
    for (int j = j0; j < j0 + 36; j++) {
        float v[2];
#pragma unroll
        for (int q = 0; q < 2; q++) {
            int k = 2*j + q;
            int din = k / 9, r = k - din*9;
            int ry = r / 3;
            int xx = x + (r - ry*3) - 1;
            v[q] = ((unsigned)xx < 32u) ? raw[din*128 + (y_local + ry)*32 + xx] : 0.f;
        }
        uint32_t u;
        if (!isLo) {
            __nv_bfloat162 h2 = __float22bfloat162_rn(make_float2(v[0], v[1]));
            memcpy(&u, &h2, 4);
            outp[p*225 + j] = u;          // t=0 (hi)
            outp[p*225 + 72 + j] = u;     // t=1 (hi dup)
        } else {
            float h0 = __bfloat162float(__float2bfloat16_rn(v[0]));
            float h1 = __bfloat162float(__float2bfloat16_rn(v[1]));
            __nv_bfloat162 l2 = __float22bfloat162_rn(make_float2(v[0]-h0, v[1]-h1));
            memcpy(&u, &l2, 4);
            outp[p*225 + 144 + j] = u;    // t=2 (lo)
        }
    }
    if (part == 3) {
#pragma unroll
        for (int jz = 216; jz < 224; jz++) outp[p*225 + jz] = 0;  // K pad
    }
    __syncthreads();
    uint32_t* gdst = (uint32_t*)((char*)g_Ab + (size_t)m064 * (KPAD*2));
    for (int i = tid; i < 64*224; i += 256)
        gdst[i] = outp[(i/224)*225 + (i%224)];
}

// ---------------- kernel: bf16 mma.sync GEMM votes = A x B^T + bias -------
// 128x128 block tile, BK=32, double-buffered cp.async, 8 warps (2M x 4N),
// warp tile 64x32 via m16n8k16. smem stride 40 bf16 (conflict-free frags).
#define SA_STR 40
__device__ __forceinline__ void load_tile(uint32_t sA, uint32_t sB,
                                          const char* Asrc, const char* Bsrc,
                                          int kstage, int tid) {
#pragma unroll
    for (int i = 0; i < 2; i++) {
        int q = i*256 + tid;
        int row = q >> 2, kc = q & 3;
        CP_ASYNC16(sA + row*(SA_STR*2) + kc*16,
                   Asrc + (size_t)row*(KPAD*2) + kstage*64 + kc*16);
    }
#pragma unroll
    for (int i = 0; i < 2; i++) {
        int q = i*256 + tid;
        int row = q >> 2, kc = q & 3;
        CP_ASYNC16(sB + row*(SA_STR*2) + kc*16,
                   Bsrc + (size_t)row*(KPAD*2) + kstage*64 + kc*16);
    }
}

__global__ __launch_bounds__(256) void k_gemm(const float* __restrict__ bt) {
    __shared__ __align__(16) __nv_bfloat16 As[2][128*SA_STR];
    __shared__ __align__(16) __nv_bfloat16 Bs[2][128*SA_STR];
    __shared__ float bias_s[128];
    const int tid = threadIdx.x;
    const int lane = tid & 31;
    const int wid = tid >> 5;
    const int warpM = wid & 1;     // 2 M-warps
    const int warpN = wid >> 1;    // 4 N-warps
    const int n0 = blockIdx.x * 128;
    const int m0 = blockIdx.y * 128;
    if (tid < 128) bias_s[tid] = bt[n0 + tid];

    const char* Asrc = (const char*)g_Ab + (size_t)m0 * (KPAD*2);
    const char* Bsrc = (const char*)g_Bb + (size_t)n0 * (KPAD*2);
    const uint32_t sA0 = smem_u32(&As[0][0]), sA1 = smem_u32(&As[1][0]);
    const uint32_t sB0 = smem_u32(&Bs[0][0]), sB1 = smem_u32(&Bs[1][0]);

    load_tile(sA0, sB0, Asrc, Bsrc, 0, tid); CP_COMMIT();
    load_tile(sA1, sB1, Asrc, Bsrc, 1, tid); CP_COMMIT();

    float acc[4][4][4];
#pragma unroll
    for (int a = 0; a < 4; a++)
#pragma unroll
        for (int b = 0; b < 4; b++)
#pragma unroll
            for (int c = 0; c < 4; c++) acc[a][b][c] = 0.f;

    const int qr = lane >> 2;   // 0..7
    const int qc = lane & 3;    // 0..3

    for (int s = 0; s < 14; s++) {
        if (s == 13) asm volatile("cp.async.wait_group 0;" ::: "memory");
        else         asm volatile("cp.async.wait_group 1;" ::: "memory");
        __syncthreads();
        const __nv_bfloat16* Ab = As[s & 1];
        const __nv_bfloat16* Bb = Bs[s & 1];
#pragma unroll
        for (int kk = 0; kk < 2; kk++) {
            uint32_t afr[4][4], bfr[4][2];
            const int cbase = kk*16 + qc*2;
#pragma unroll
            for (int mf = 0; mf < 4; mf++) {
                int row = warpM*64 + mf*16 + qr;
                afr[mf][0] = *(const uint32_t*)&Ab[row*SA_STR + cbase];
                afr[mf][1] = *(const uint32_t*)&Ab[(row+8)*SA_STR + cbase];
                afr[mf][2] = *(const uint32_t*)&Ab[row*SA_STR + cbase + 8];
                afr[mf][3] = *(const uint32_t*)&Ab[(row+8)*SA_STR + cbase + 8];
            }
#pragma unroll
            for (int nf = 0; nf < 4; nf++) {
                int nn = warpN*32 + nf*8 + qr;
                bfr[nf][0] = *(const uint32_t*)&Bb[nn*SA_STR + cbase];
                bfr[nf][1] = *(const uint32_t*)&Bb[nn*SA_STR + cbase + 8];
            }
#pragma unroll
            for (int mf = 0; mf < 4; mf++)
#pragma unroll
                for (int nf = 0; nf < 4; nf++) {
                    asm volatile(
                        "mma.sync.aligned.m16n8k16.row.col.f32.bf16.bf16.f32 "
                        "{%0,%1,%2,%3}, {%4,%5,%6,%7}, {%8,%9}, {%0,%1,%2,%3};"
                        : "+f"(acc[mf][nf][0]), "+f"(acc[mf][nf][1]),
                          "+f"(acc[mf][nf][2]), "+f"(acc[mf][nf][3])
                        : "r"(afr[mf][0]), "r"(afr[mf][1]), "r"(afr[mf][2]), "r"(afr[mf][3]),
                          "r"(bfr[nf][0]), "r"(bfr[nf][1]));
                }
        }
        __syncthreads();
        if (s + 2 < 14) {
            if (s & 1) load_tile(sA1, sB1, Asrc, Bsrc, s + 2, tid);
            else       load_tile(sA0, sB0, Asrc, Bsrc, s + 2, tid);
            CP_COMMIT();
        }
    }

    // epilogue: + bias, direct stores
#pragma unroll
    for (int mf = 0; mf < 4; mf++) {
        int row0 = m0 + warpM*64 + mf*16 + qr;
#pragma unroll
        for (int nf = 0; nf < 4; nf++) {
            int cl = warpN*32 + nf*8 + qc*2;
            float b0 = bias_s[cl], b1 = bias_s[cl + 1];
            float2 o0 = make_float2(acc[mf][nf][0] + b0, acc[mf][nf][1] + b1);
            float2 o1 = make_float2(acc[mf][nf][2] + b0, acc[mf][nf][3] + b1);
            *(float2*)(g_votes + (size_t)row0*1024 + n0 + cl) = o0;
            *(float2*)(g_votes + (size_t)(row0+8)*1024 + n0 + cl) = o1;
        }
    }
}

// ---------------- kernel 2: values + pooling + agreement routing ----------
// c2-outer / kp-inner; softmax weights via w_c = 1/std_c (min-std stabilizer
// cancels). launch_bounds(256,4) caps regs at 64 -> 4 blocks/SM (occ 50%).
__global__ __launch_bounds__(256, 4) void k_route(const float* __restrict__ Wv,
                                                  const float* __restrict__ bv) {
    __shared__ __align__(16) float wv_s[2048];
    __shared__ float bv_s[256];
    int tid = threadIdx.x;
    for (int i = tid; i < 2048; i += 256) wv_s[i] = Wv[i];
    if (tid < 256) bv_s[tid] = bv[tid];
    __syncthreads();

    int pt   = blockIdx.x * 8 + (tid >> 5);
    int lane = tid & 31;
    int o    = lane >> 2;
    const float* vp = g_votes + pt * 1024;

    u64 vt2[8][2];
#pragma unroll
    for (int c = 0; c < 8; c++) {
        ulonglong2 t = *(const ulonglong2*)(vp + c*128 + lane*4);
        vt2[c][0] = t.x; vt2[c][1] = t.y;
    }

    float av[4] = {0.f, 0.f, 0.f, 0.f};
    float wsum[4] = {0.f, 0.f, 0.f, 0.f};
    float pmax[4] = {-1e30f, -1e30f, -1e30f, -1e30f};
    u64 psum2[2] = {0ULL, 0ULL};

    const float4* wv4 = (const float4*)wv_s;
#pragma unroll
    for (int c2 = 0; c2 < 8; c2++) {
        u64 ks0 = 0ULL, ks1 = 0ULL, kq0 = 0ULL, kq1 = 0ULL;
#pragma unroll
        for (int kp = 0; kp < 4; kp++) {
            int m = kp*8 + c2;
            float4 wa = wv4[(o*32 + m)*2 + 0];
            float4 wb = wv4[(o*32 + m)*2 + 1];
            float bvv = bv_s[o*32 + m];
            u64 bb = pack2(bvv, bvv);
            u64 v0 = bb, v1 = bb, w;
            w = pack2(wa.x, wa.x); v0 = ffma2(w, vt2[0][0], v0); v1 = ffma2(w, vt2[0][1], v1);
            w = pack2(wa.y, wa.y); v0 = ffma2(w, vt2[1][0], v0); v1 = ffma2(w, vt2[1][1], v1);
            w = pack2(wa.z, wa.z); v0 = ffma2(w, vt2[2][0], v0); v1 = ffma2(w, vt2[2][1], v1);
            w = pack2(wa.w, wa.w); v0 = ffma2(w, vt2[3][0], v0); v1 = ffma2(w, vt2[3][1], v1);
            w = pack2(wb.x, wb.x); v0 = ffma2(w, vt2[4][0], v0); v1 = ffma2(w, vt2[4][1], v1);
            w = pack2(wb.y, wb.y); v0 = ffma2(w, vt2[5][0], v0); v1 = ffma2(w, vt2[5][1], v1);
            w = pack2(wb.z, wb.z); v0 = ffma2(w, vt2[6][0], v0); v1 = ffma2(w, vt2[6][1], v1);
            w = pack2(wb.w, wb.w); v0 = ffma2(w, vt2[7][0], v0); v1 = ffma2(w, vt2[7][1], v1);
            ks0 = fadd2(ks0, v0);
            ks1 = fadd2(ks1, v1);
            kq0 = ffma2(v0, v0, kq0);
            kq1 = ffma2(v1, v1, kq1);
            psum2[0] = fadd2(psum2[0], v0);
            psum2[1] = fadd2(psum2[1], v1);
            float f0, f1, f2, f3;
            unpack2(v0, f0, f1); unpack2(v1, f2, f3);
            pmax[0] = fmaxf(pmax[0], f0);
            pmax[1] = fmaxf(pmax[1], f1);
            pmax[2] = fmaxf(pmax[2], f2);
            pmax[3] = fmaxf(pmax[3], f3);
        }
        float ksf[4], kqf[4];
        unpack2(ks0, ksf[0], ksf[1]); unpack2(ks1, ksf[2], ksf[3]);
        unpack2(kq0, kqf[0], kqf[1]); unpack2(kq1, kqf[2], kqf[3]);
#pragma unroll
        for (int j = 0; j < 4; j++) {
            float mu  = ksf[j] * 0.25f;
            float var = fmaxf(kqf[j] * 0.25f - mu*mu, 1e-30f);
            float rs  = rsqrtf(var);       // = 1/std
            av[j]   += mu * rs;
            wsum[j] += rs;
        }
    }

    float sA[4], pMe[4];
    float pf0, pf1, pf2, pf3;
    unpack2(psum2[0], pf0, pf1); unpack2(psum2[1], pf2, pf3);
    pMe[0] = pf0 * (1.f/32.f); pMe[1] = pf1 * (1.f/32.f);
    pMe[2] = pf2 * (1.f/32.f); pMe[3] = pf3 * (1.f/32.f);
#pragma unroll
    for (int j = 0; j < 4; j++) sA[j] = av[j] / wsum[j];

    int off = pt*128 + lane*4;
    *(float4*)(g_sumAtt + off) = make_float4(sA[0], sA[1], sA[2], sA[3]);
    *(float4*)(g_pmax   + off) = make_float4(pmax[0], pmax[1], pmax[2], pmax[3]);
    *(float4*)(g_pmean  + off) = make_float4(pMe[0], pMe[1], pMe[2], pMe[3]);
}

// ---------------- kernel 3: 3D gate conv (3x3x3, pad1) + BN partials -----
// warp = one point; lane = (o,q): fully-coalesced 512B neighborhood loads,
// dz-halo via quad shuffles. grid NPTS/8 = 4096.
__global__ __launch_bounds__(256) void k_gate(const float* __restrict__ Ws) {
    __shared__ float ws_s[54];
    __shared__ float bsum[8], bss[8];
    int tid = threadIdx.x;
    if (tid < 54) ws_s[tid] = Ws[tid];
    if (tid < 8) { bsum[tid] = 0.f; bss[tid] = 0.f; }
    __syncthreads();

    const unsigned FULL = 0xffffffffu;
    int wid = tid >> 5, lane = tid & 31;
    int o = lane >> 2, q = lane & 3;
    int pt = blockIdx.x * 8 + wid;
    int b = pt >> 10, yx = pt & 1023;
    int y = yx >> 5, x = yx & 31;

    float acc[4] = {0.f, 0.f, 0.f, 0.f};

    for (int dy = -1; dy <= 1; dy++) {
        int yy = y + dy;
        if ((unsigned)yy >= 32u) continue;
        for (int dx = -1; dx <= 1; dx++) {
            int xx = x + dx;
            if ((unsigned)xx >= 32u) continue;
            int base = ((b << 10) + (yy << 5) + xx)*128 + (o << 4) + (q << 2);
            int wo = (dy+1)*3 + (dx+1);
            float4 vx = *(const float4*)(g_pmax  + base);
            float4 vn = *(const float4*)(g_pmean + base);
            float xm1 = __shfl_up_sync(FULL, vx.w, 1, 4);
            float xp1 = __shfl_down_sync(FULL, vx.x, 1, 4);
            float nm1 = __shfl_up_sync(FULL, vn.w, 1, 4);
            float np1 = __shfl_down_sync(FULL, vn.x, 1, 4);
            if (q == 0) { xm1 = 0.f; nm1 = 0.f; }
            if (q == 3) { xp1 = 0.f; np1 = 0.f; }
            float wx[6] = {xm1, vx.x, vx.y, vx.z, vx.w, xp1};
            float wn[6] = {nm1, vn.x, vn.y, vn.z, vn.w, np1};
            float wm0 = ws_s[0*9 + wo], wm1 = ws_s[9 + wo], wm2 = ws_s[18 + wo];
            float wq0 = ws_s[27 + wo],  wq1 = ws_s[36 + wo], wq2 = ws_s[45 + wo];
#pragma unroll
            for (int j = 0; j < 4; j++) {
                acc[j] += wm0*wx[j] + wm1*wx[j+1] + wm2*wx[j+2]
                        + wq0*wn[j] + wq1*wn[j+1] + wq2*wn[j+2];
            }
        }
    }

    *(float4*)(g_gate + pt*128 + (o << 4) + (q << 2)) =
        make_float4(acc[0], acc[1], acc[2], acc[3]);

    float s1 = acc[0] + acc[1] + acc[2] + acc[3];
    float s2 = acc[0]*acc[0] + acc[1]*acc[1] + acc[2]*acc[2] + acc[3]*acc[3];
    s1 += __shfl_xor_sync(FULL, s1, 1, 4);
    s2 += __shfl_xor_sync(FULL, s2, 1, 4);
    s1 += __shfl_xor_sync(FULL, s1, 2, 4);
    s2 += __shfl_xor_sync(FULL, s2, 2, 4);
    if (q == 0) { atomicAdd(&bsum[o], s1); atomicAdd(&bss[o], s2); }
    __syncthreads();
    if (tid < 8) {
        g_psumArr[blockIdx.x*8 + tid] = bsum[tid];
        g_pssArr [blockIdx.x*8 + tid] = bss[tid];
    }
}

// ---------------- kernel 3b: BN stats finalize (4096 partials) ------------
__global__ void k_bnstats() {
    __shared__ float ss1[256], ss2[256];
    int tid = threadIdx.x;
    int o = tid & 7, seg = tid >> 3;
    float a = 0.f, c = 0.f;
    for (int i = seg*128; i < seg*128 + 128; i++) {
        a += g_psumArr[i*8 + o];
        c += g_pssArr [i*8 + o];
    }
    ss1[tid] = a; ss2[tid] = c;
    __syncthreads();
    if (tid < 8) {
        float A = 0.f, C = 0.f;
        for (int s = 0; s < 32; s++) { A += ss1[s*8 + tid]; C += ss2[s*8 + tid]; }
        const float inv = 1.f / 524288.f;
        float mu = A * inv;
        float var = C * inv - mu*mu;
        g_bnMu[tid]   = mu;
        g_bnRstd[tid] = rsqrtf(var + EPSV);
    }
}

// ---------------- kernel 4: gate apply + LayerNorm + transpose out -------
#define SM4_STRIDE 1025
__global__ __launch_bounds__(256) void k_final(const float* __restrict__ bn_gamma,
                                               const float* __restrict__ bn_beta,
                                               const float* __restrict__ ln_gamma,
                                               const float* __restrict__ ln_beta,
                                               float* __restrict__ out) {
    extern __shared__ float sm4[];
    const int RED = 16*SM4_STRIDE;
    int tid = threadIdx.x;
    int b = blockIdx.x & 31;
    int o = blockIdx.x >> 5;
    float mu = g_bnMu[o], rstd = g_bnRstd[o];
    float gam = bn_gamma[0], bet = bn_beta[0];

    int d   = tid & 15;
    int yxb = tid >> 4;
    const float* gp = g_gate   + (b << 10)*128 + (o << 4) + d;
    const float* sp = g_sumAtt + (b << 10)*128 + (o << 4) + d;
    float s = 0.f, ss = 0.f;
    for (int i = 0; i < 64; i++) {
        int yx = yxb + i*16;
        float gg = gp[yx*128];
        float sa = sp[yx*128];
        float z  = (gg - mu) * rstd * gam + bet;
        float sc = 1.f / (1.f + expf(-z));
        float cn = (1.f + sc) * sa;
        sm4[d*SM4_STRIDE + yx] = cn;
        s += cn; ss += cn*cn;
    }
#pragma unroll
    for (int off = 16; off >= 1; off >>= 1) {
        s  += __shfl_xor_sync(0xffffffffu, s,  off);
        ss += __shfl_xor_sync(0xffffffffu, ss, off);
    }
    int wid = tid >> 5;
    if ((tid & 31) == 0) { sm4[RED + wid] = s; sm4[RED + 8 + wid] = ss; }
    __syncthreads();
    if (tid == 0) {
        float S = 0.f, Q = 0.f;
        for (int w = 0; w < 8; w++) { S += sm4[RED + w]; Q += sm4[RED + 8 + w]; }
        const float inv = 1.f / 16384.f;
        float m = S * inv;
        float var = Q * inv - m*m;
        sm4[RED + 16] = m;
        sm4[RED + 17] = rsqrtf(var + EPSV);
    }
    __syncthreads();
    float m = sm4[RED + 16], r = sm4[RED + 17];
    float* ob = out + ((o*32 + b) << 14);
    for (int i = 0; i < 64; i++) {
        int idx = i*256 + tid;
        float v = sm4[(idx >> 10)*SM4_STRIDE + (idx & 1023)];
        ob[idx] = (v - m) * r * ln_gamma[idx] + ln_beta[idx];
    }
}

// ---------------- launch ------------------------------------------------
extern "C" void kernel_launch(void* const* d_in, const int* in_sizes, int n_in,
                              void* d_out, int out_size) {
    const float* caps = (const float*)d_in[0];
    const float* Wt   = (const float*)d_in[1];
    const float* bt   = (const float*)d_in[2];
    const float* Wv   = (const float*)d_in[3];
    const float* bv   = (const float*)d_in[4];
    const float* Ws   = (const float*)d_in[5];
    const float* bng  = (const float*)d_in[6];
    const float* bnb  = (const float*)d_in[7];
    const float* lng  = (const float*)d_in[8];
    const float* lnb  = (const float*)d_in[9];
    float* out = (float*)d_out;

    const int smemA = 8192 + 64*225*4;            // 65792
    const int smem4 = (16*SM4_STRIDE + 32) * 4;
    cudaFuncSetAttribute(k_prepA, cudaFuncAttributeMaxDynamicSharedMemorySize, smemA);
    cudaFuncSetAttribute(k_final, cudaFuncAttributeMaxDynamicSharedMemorySize, smem4);

    k_prepB<<<1792, 256>>>(Wt);
    k_prepA<<<512, 256, smemA>>>(caps);
    k_gemm<<<dim3(8, 256), 256>>>(bt);
    k_route<<<NPTS/8, 256>>>(Wv, bv);
    k_gate<<<NPTS/8, 256>>>(Ws);
    k_bnstats<<<1, 256>>>();
    k_final<<<256, 256, smem4>>>(bng, bnb, lng, lnb, out);
}

// round 7
// speedup vs baseline: 1.1158x; 1.1158x over previous
#include <cuda_runtime.h>
#include <cuda_bf16.h>
#include <math.h>
#include <stdint.h>
#include <string.h>

// Problem constants
#define BATCH 32
#define CIN   8
#define COUT  8
#define KP    4
#define DIN   16
#define DOUT  16
#define SS_   32
#define EPSV  1e-5f

#define NPTS  (BATCH*SS_*SS_)      // 32768 spatial points (b,y,x)
#define NOC   (CIN*COUT*DOUT)      // 1024 conv output channels
#define KDIM  (DIN*9)              // 144 GEMM K (fp32)
#define KEFF  432                  // 3*144 split-bf16 K
#define KPAD  448                  // padded: 14 stages of BK=32
#define OD    (COUT*DOUT)          // 128 (o,d) pairs per point

typedef unsigned long long u64;

// ---------------- packed f32x2 helpers ------------------------------------
__device__ __forceinline__ u64 pack2(float lo, float hi) {
    u64 d; asm("mov.b64 %0,{%1,%2};" : "=l"(d) : "f"(lo), "f"(hi)); return d;
}
__device__ __forceinline__ u64 ffma2(u64 a, u64 b, u64 c) {
    u64 d; asm("fma.rn.f32x2 %0,%1,%2,%3;" : "=l"(d) : "l"(a), "l"(b), "l"(c)); return d;
}
__device__ __forceinline__ u64 fadd2(u64 a, u64 b) {
    u64 d; asm("add.rn.f32x2 %0,%1,%2;" : "=l"(d) : "l"(a), "l"(b)); return d;
}
__device__ __forceinline__ void unpack2(u64 d, float& lo, float& hi) {
    asm("mov.b64 {%0,%1},%2;" : "=f"(lo), "=f"(hi) : "l"(d));
}

__device__ __forceinline__ uint32_t smem_u32(const void* p) {
    uint32_t a;
    asm("{ .reg .u64 t; cvta.to.shared.u64 t, %1; cvt.u32.u64 %0, t; }" : "=r"(a) : "l"(p));
    return a;
}
#define CP_ASYNC16(dst, src) asm volatile("cp.async.cg.shared.global [%0], [%1], 16;" :: "r"(dst), "l"(src))
#define CP_COMMIT()          asm volatile("cp.async.commit_group;" ::: "memory")

// ---------------- scratch (device globals) --------------------------------
__device__ __align__(128) __nv_bfloat16 g_Ab[NPTS*KPAD];   // split-bf16 im2col A [p][e]
__device__ __align__(128) __nv_bfloat16 g_Bb[NOC*KPAD];    // split-bf16 weights [oc][e]
__device__ __align__(128) float g_votes[NPTS*NOC];         // conv output [pt][oc]
__device__ __align__(128) float g_sumAtt[NPTS*OD];
__device__ __align__(128) float g_pmax[NPTS*OD];
__device__ __align__(128) float g_pmean[NPTS*OD];
__device__ __align__(128) float g_gate[NPTS*OD];
__device__ float g_psumArr[4096*8];
__device__ float g_pssArr[4096*8];
__device__ float g_bnMu[8];
__device__ float g_bnRstd[8];

// ---------------- kernel: prep B (split Wt -> bf16 [oc][448]) -------------
// A terms: [hi, hi, lo]; B terms: [hi, lo, hi]  => hi*hi + hi*lo + lo*hi
__global__ void k_prepB(const float* __restrict__ Wt) {
    int idx = blockIdx.x * 256 + threadIdx.x;   // 1792 blocks exact
    int oc = idx / KPAD, e = idx % KPAD;
    float v = 0.f;
    if (e < KEFF) {
        int t = e / KDIM, k = e - t*KDIM;
        float w = Wt[oc*KDIM + k];
        float hi = __bfloat162float(__float2bfloat16_rn(w));
        v = (t == 1) ? (w - hi) : hi;
    }
    g_Bb[idx] = __float2bfloat16_rn(v);
}

// ---------------- kernel: prep A (im2col + split -> bf16 [p][448]) --------
// block = 64 points (2 y-rows of one image). grid 512.
__global__ __launch_bounds__(256) void k_prepA(const float* __restrict__ caps) {
    extern __shared__ char sm[];
    float* raw = (float*)sm;                       // 16 din x 4 rows x 32 = 2048 f
    uint32_t* outp = (uint32_t*)(sm + 8192);       // [64][225] u32 (padded stride)
    int tid = threadIdx.x;
    int m064 = blockIdx.x * 64;
    int b = m064 >> 10;
    int y0 = (m064 & 1023) >> 5;
    for (int i = tid; i < 2048; i += 256) {
        int din = i >> 7, rem = i & 127, yy = y0 - 1 + (rem >> 5), x = rem & 31;
        raw[i] = ((unsigned)yy < 32u) ? caps[b*16384 + din*1024 + yy*32 + x] : 0.f;
    }
    __syncthreads();
    int p = tid & 63, part = tid >> 6;
    int y_local = p >> 5, x = p & 31;
    bool isLo = part >= 2;
    int j0 = (part & 1) * 36;
    for (int j = j0; j < j0 + 36; j++) {
        float v[2];
#pragma unroll
        for (int q = 0; q < 2; q++) {
            int k = 2*j + q;
            int din = k / 9, r = k - din*9;
            int ry = r / 3;
            int xx = x + (r - ry*3) - 1;
            v[q] = ((unsigned)xx < 32u) ? raw[din*128 + (y_local + ry)*32 + xx] : 0.f;
        }
        uint32_t u;
        if (!isLo) {
            __nv_bfloat162 h2 = __float22bfloat162_rn(make_float2(v[0], v[1]));
            memcpy(&u, &h2, 4);
            outp[p*225 + j] = u;          // t=0 (hi)
            outp[p*225 + 72 + j] = u;     // t=1 (hi dup)
        } else {
            float h0 = __bfloat162float(__float2bfloat16_rn(v[0]));
            float h1 = __bfloat162float(__float2bfloat16_rn(v[1]));
            __nv_bfloat162 l2 = __float22bfloat162_rn(make_float2(v[0]-h0, v[1]-h1));
            memcpy(&u, &l2, 4);
            outp[p*225 + 144 + j] = u;    // t=2 (lo)
        }
    }
    if (part == 3) {
#pragma unroll
        for (int jz = 216; jz < 224; jz++) outp[p*225 + jz] = 0;  // K pad
    }
    __syncthreads();
    uint32_t* gdst = (uint32_t*)((char*)g_Ab + (size_t)m064 * (KPAD*2));
    for (int i = tid; i < 64*224; i += 256)
        gdst[i] = outp[(i/224)*225 + (i%224)];
}

// ---------------- kernel: bf16 mma.sync GEMM votes = A x B^T + bias -------
// 128x128 block tile, BK=32, double-buffered cp.async, 8 warps (2M x 4N),
// warp tile 64x32 via m16n8k16. smem stride 40 bf16 (conflict-free frags).
#define SA_STR 40
__device__ __forceinline__ void load_tile(uint32_t sA, uint32_t sB,
                                          const char* Asrc, const char* Bsrc,
                                          int kstage, int tid) {
#pragma unroll
    for (int i = 0; i < 2; i++) {
        int q = i*256 + tid;
        int row = q >> 2, kc = q & 3;
        CP_ASYNC16(sA + row*(SA_STR*2) + kc*16,
                   Asrc + (size_t)row*(KPAD*2) + kstage*64 + kc*16);
    }
#pragma unroll
    for (int i = 0; i < 2; i++) {
        int q = i*256 + tid;
        int row = q >> 2, kc = q & 3;
        CP_ASYNC16(sB + row*(SA_STR*2) + kc*16,
                   Bsrc + (size_t)row*(KPAD*2) + kstage*64 + kc*16);
    }
}

__global__ __launch_bounds__(256) void k_gemm(const float* __restrict__ bt) {
    __shared__ __align__(16) __nv_bfloat16 As[2][128*SA_STR];
    __shared__ __align__(16) __nv_bfloat16 Bs[2][128*SA_STR];
    __shared__ float bias_s[128];
    const int tid = threadIdx.x;
    const int lane = tid & 31;
    const int wid = tid >> 5;
    const int warpM = wid & 1;     // 2 M-warps
    const int warpN = wid >> 1;    // 4 N-warps
    const int n0 = blockIdx.x * 128;
    const int m0 = blockIdx.y * 128;
    if (tid < 128) bias_s[tid] = bt[n0 + tid];

    const char* Asrc = (const char*)g_Ab + (size_t)m0 * (KPAD*2);
    const char* Bsrc = (const char*)g_Bb + (size_t)n0 * (KPAD*2);
    const uint32_t sA0 = smem_u32(&As[0][0]), sA1 = smem_u32(&As[1][0]);
    const uint32_t sB0 = smem_u32(&Bs[0][0]), sB1 = smem_u32(&Bs[1][0]);

    load_tile(sA0, sB0, Asrc, Bsrc, 0, tid); CP_COMMIT();
    load_tile(sA1, sB1, Asrc, Bsrc, 1, tid); CP_COMMIT();

    float acc[4][4][4];
#pragma unroll
    for (int a = 0; a < 4; a++)
#pragma unroll
        for (int b = 0; b < 4; b++)
#pragma unroll
            for (int c = 0; c < 4; c++) acc[a][b][c] = 0.f;

    const int qr = lane >> 2;   // 0..7
    const int qc = lane & 3;    // 0..3

    for (int s = 0; s < 14; s++) {
        if (s == 13) asm volatile("cp.async.wait_group 0;" ::: "memory");
        else         asm volatile("cp.async.wait_group 1;" ::: "memory");
        __syncthreads();
        const __nv_bfloat16* Ab = As[s & 1];
        const __nv_bfloat16* Bb = Bs[s & 1];
#pragma unroll
        for (int kk = 0; kk < 2; kk++) {
            uint32_t afr[4][4], bfr[4][2];
            const int cbase = kk*16 + qc*2;
#pragma unroll
            for (int mf = 0; mf < 4; mf++) {
                int row = warpM*64 + mf*16 + qr;
                afr[mf][0] = *(const uint32_t*)&Ab[row*SA_STR + cbase];
                afr[mf][1] = *(const uint32_t*)&Ab[(row+8)*SA_STR + cbase];
                afr[mf][2] = *(const uint32_t*)&Ab[row*SA_STR + cbase + 8];
                afr[mf][3] = *(const uint32_t*)&Ab[(row+8)*SA_STR + cbase + 8];
            }
#pragma unroll
            for (int nf = 0; nf < 4; nf++) {
                int nn = warpN*32 + nf*8 + qr;
                bfr[nf][0] = *(const uint32_t*)&Bb[nn*SA_STR + cbase];
                bfr[nf][1] = *(const uint32_t*)&Bb[nn*SA_STR + cbase + 8];
            }
#pragma unroll
            for (int mf = 0; mf < 4; mf++)
#pragma unroll
                for (int nf = 0; nf < 4; nf++) {
                    asm volatile(
                        "mma.sync.aligned.m16n8k16.row.col.f32.bf16.bf16.f32 "
                        "{%0,%1,%2,%3}, {%4,%5,%6,%7}, {%8,%9}, {%0,%1,%2,%3};"
                        : "+f"(acc[mf][nf][0]), "+f"(acc[mf][nf][1]),
                          "+f"(acc[mf][nf][2]), "+f"(acc[mf][nf][3])
                        : "r"(afr[mf][0]), "r"(afr[mf][1]), "r"(afr[mf][2]), "r"(afr[mf][3]),
                          "r"(bfr[nf][0]), "r"(bfr[nf][1]));
                }
        }
        __syncthreads();
        if (s + 2 < 14) {
            if (s & 1) load_tile(sA1, sB1, Asrc, Bsrc, s + 2, tid);
            else       load_tile(sA0, sB0, Asrc, Bsrc, s + 2, tid);
            CP_COMMIT();
        }
    }

    // epilogue: + bias, direct stores
#pragma unroll
    for (int mf = 0; mf < 4; mf++) {
        int row0 = m0 + warpM*64 + mf*16 + qr;
#pragma unroll
        for (int nf = 0; nf < 4; nf++) {
            int cl = warpN*32 + nf*8 + qc*2;
            float b0 = bias_s[cl], b1 = bias_s[cl + 1];
            float2 o0 = make_float2(acc[mf][nf][0] + b0, acc[mf][nf][1] + b1);
            float2 o1 = make_float2(acc[mf][nf][2] + b0, acc[mf][nf][3] + b1);
            *(float2*)(g_votes + (size_t)row0*1024 + n0 + cl) = o0;
            *(float2*)(g_votes + (size_t)(row0+8)*1024 + n0 + cl) = o1;
        }
    }
}

// ---------------- kernel 2: values + pooling + agreement routing ----------
// 64 threads per point; each thread owns one (o, d-pair). Live set: 8 u64
// vote regs (vs 16 before) -> ~55 regs, 4-5 blocks/SM naturally, no cap.
// softmax weights via w_c = 1/std_c (min-std stabilizer cancels).
__global__ __launch_bounds__(256) void k_route(const float* __restrict__ Wv,
                                               const float* __restrict__ bv) {
    __shared__ __align__(16) float wv_s[2048];
    __shared__ float bv_s[256];
    int tid = threadIdx.x;
    for (int i = tid; i < 2048; i += 256) wv_s[i] = Wv[i];
    if (tid < 256) bv_s[tid] = bv[tid];
    __syncthreads();

    int pt  = blockIdx.x * 4 + (tid >> 6);
    int l64 = tid & 63;            // (o, dq): o = l64>>3, dq = l64&7
    int o   = l64 >> 3;
    const float* vp = g_votes + (size_t)pt * 1024 + l64 * 2;

    u64 vt2[8];
#pragma unroll
    for (int c = 0; c < 8; c++)
        vt2[c] = *(const u64*)(vp + c*128);

    float av[2] = {0.f, 0.f};
    float wsum[2] = {0.f, 0.f};
    float pmax[2] = {-1e30f, -1e30f};
    u64 psum2 = 0ULL;

    const float4* wv4 = (const float4*)wv_s;
#pragma unroll
    for (int c2 = 0; c2 < 8; c2++) {
        u64 ks = 0ULL, kq = 0ULL;
#pragma unroll
        for (int kp = 0; kp < 4; kp++) {
            int m = kp*8 + c2;
            float4 wa = wv4[(o*32 + m)*2 + 0];
            float4 wb = wv4[(o*32 + m)*2 + 1];
            float bvv = bv_s[o*32 + m];
            u64 v0 = pack2(bvv, bvv), w;
            w = pack2(wa.x, wa.x); v0 = ffma2(w, vt2[0], v0);
            w = pack2(wa.y, wa.y); v0 = ffma2(w, vt2[1], v0);
            w = pack2(wa.z, wa.z); v0 = ffma2(w, vt2[2], v0);
            w = pack2(wa.w, wa.w); v0 = ffma2(w, vt2[3], v0);
            w = pack2(wb.x, wb.x); v0 = ffma2(w, vt2[4], v0);
            w = pack2(wb.y, wb.y); v0 = ffma2(w, vt2[5], v0);
            w = pack2(wb.z, wb.z); v0 = ffma2(w, vt2[6], v0);
            w = pack2(wb.w, wb.w); v0 = ffma2(w, vt2[7], v0);
            ks = fadd2(ks, v0);
            kq = ffma2(v0, v0, kq);
            psum2 = fadd2(psum2, v0);
            float f0, f1;
            unpack2(v0, f0, f1);
            pmax[0] = fmaxf(pmax[0], f0);
            pmax[1] = fmaxf(pmax[1], f1);
        }
        float ksf0, ksf1, kqf0, kqf1;
        unpack2(ks, ksf0, ksf1);
        unpack2(kq, kqf0, kqf1);
        {
            float mu  = ksf0 * 0.25f;
            float var = fmaxf(kqf0 * 0.25f - mu*mu, 1e-30f);
            float rs  = rsqrtf(var);
            av[0] += mu * rs; wsum[0] += rs;
        }
        {
            float mu  = ksf1 * 0.25f;
            float var = fmaxf(kqf1 * 0.25f - mu*mu, 1e-30f);
            float rs  = rsqrtf(var);
            av[1] += mu * rs; wsum[1] += rs;
        }
    }

    float pf0, pf1;
    unpack2(psum2, pf0, pf1);
    size_t off = (size_t)pt*128 + l64*2;
    *(float2*)(g_sumAtt + off) = make_float2(av[0]/wsum[0], av[1]/wsum[1]);
    *(float2*)(g_pmax   + off) = make_float2(pmax[0], pmax[1]);
    *(float2*)(g_pmean  + off) = make_float2(pf0 * (1.f/32.f), pf1 * (1.f/32.f));
}

// ---------------- kernel 3: 3D gate conv (3x3x3, pad1) + BN partials -----
// warp = one point; lane = (o,q): fully-coalesced 512B neighborhood loads,
// dz-halo via quad shuffles. grid NPTS/8 = 4096.
__global__ __launch_bounds__(256) void k_gate(const float* __restrict__ Ws) {
    __shared__ float ws_s[54];
    __shared__ float bsum[8], bss[8];
    int tid = threadIdx.x;
    if (tid < 54) ws_s[tid] = Ws[tid];
    if (tid < 8) { bsum[tid] = 0.f; bss[tid] = 0.f; }
    __syncthreads();

    const unsigned FULL = 0xffffffffu;
    int wid = tid >> 5, lane = tid & 31;
    int o = lane >> 2, q = lane & 3;
    int pt = blockIdx.x * 8 + wid;
    int b = pt >> 10, yx = pt & 1023;
    int y = yx >> 5, x = yx & 31;

    float acc[4] = {0.f, 0.f, 0.f, 0.f};

    for (int dy = -1; dy <= 1; dy++) {
        int yy = y + dy;
        if ((unsigned)yy >= 32u) continue;
        for (int dx = -1; dx <= 1; dx++) {
            int xx = x + dx;
            if ((unsigned)xx >= 32u) continue;
            int base = ((b << 10) + (yy << 5) + xx)*128 + (o << 4) + (q << 2);
            int wo = (dy+1)*3 + (dx+1);
            float4 vx = *(const float4*)(g_pmax  + base);
            float4 vn = *(const float4*)(g_pmean + base);
            float xm1 = __shfl_up_sync(FULL, vx.w, 1, 4);
            float xp1 = __shfl_down_sync(FULL, vx.x, 1, 4);
            float nm1 = __shfl_up_sync(FULL, vn.w, 1, 4);
            float np1 = __shfl_down_sync(FULL, vn.x, 1, 4);
            if (q == 0) { xm1 = 0.f; nm1 = 0.f; }
            if (q == 3) { xp1 = 0.f; np1 = 0.f; }
            float wx[6] = {xm1, vx.x, vx.y, vx.z, vx.w, xp1};
            float wn[6] = {nm1, vn.x, vn.y, vn.z, vn.w, np1};
            float wm0 = ws_s[0*9 + wo], wm1 = ws_s[9 + wo], wm2 = ws_s[18 + wo];
            float wq0 = ws_s[27 + wo],  wq1 = ws_s[36 + wo], wq2 = ws_s[45 + wo];
#pragma unroll
            for (int j = 0; j < 4; j++) {
                acc[j] += wm0*wx[j] + wm1*wx[j+1] + wm2*wx[j+2]
                        + wq0*wn[j] + wq1*wn[j+1] + wq2*wn[j+2];
            }
        }
    }

    *(float4*)(g_gate + pt*128 + (o << 4) + (q << 2)) =
        make_float4(acc[0], acc[1], acc[2], acc[3]);

    float s1 = acc[0] + acc[1] + acc[2] + acc[3];
    float s2 = acc[0]*acc[0] + acc[1]*acc[1] + acc[2]*acc[2] + acc[3]*acc[3];
    s1 += __shfl_xor_sync(FULL, s1, 1, 4);
    s2 += __shfl_xor_sync(FULL, s2, 1, 4);
    s1 += __shfl_xor_sync(FULL, s1, 2, 4);
    s2 += __shfl_xor_sync(FULL, s2, 2, 4);
    if (q == 0) { atomicAdd(&bsum[o], s1); atomicAdd(&bss[o], s2); }
    __syncthreads();
    if (tid < 8) {
        g_psumArr[blockIdx.x*8 + tid] = bsum[tid];
        g_pssArr [blockIdx.x*8 + tid] = bss[tid];
    }
}

// ---------------- kernel 3b: BN stats finalize (4096 partials) ------------
__global__ void k_bnstats() {
    __shared__ float ss1[256], ss2[256];
    int tid = threadIdx.x;
    int o = tid & 7, seg = tid >> 3;
    float a = 0.f, c = 0.f;
    for (int i = seg*128; i < seg*128 + 128; i++) {
        a += g_psumArr[i*8 + o];
        c += g_pssArr [i*8 + o];
    }
    ss1[tid] = a; ss2[tid] = c;
    __syncthreads();
    if (tid < 8) {
        float A = 0.f, C = 0.f;
        for (int s = 0; s < 32; s++) { A += ss1[s*8 + tid]; C += ss2[s*8 + tid]; }
        const float inv = 1.f / 524288.f;
        float mu = A * inv;
        float var = C * inv - mu*mu;
        g_bnMu[tid]   = mu;
        g_bnRstd[tid] = rsqrtf(var + EPSV);
    }
}

// ---------------- kernel 4: gate apply + LayerNorm + transpose out -------
#define SM4_STRIDE 1025
__global__ __launch_bounds__(256) void k_final(const float* __restrict__ bn_gamma,
                                               const float* __restrict__ bn_beta,
                                               const float* __restrict__ ln_gamma,
                                               const float* __restrict__ ln_beta,
                                               float* __restrict__ out) {
    extern __shared__ float sm4[];
    const int RED = 16*SM4_STRIDE;
    int tid = threadIdx.x;
    int b = blockIdx.x & 31;
    int o = blockIdx.x >> 5;
    float mu = g_bnMu[o], rstd = g_bnRstd[o];
    float gam = bn_gamma[0], bet = bn_beta[0];

    int d   = tid & 15;
    int yxb = tid >> 4;
    const float* gp = g_gate   + (b << 10)*128 + (o << 4) + d;
    const float* sp = g_sumAtt + (b << 10)*128 + (o << 4) + d;
    float s = 0.f, ss = 0.f;
    for (int i = 0; i < 64; i++) {
        int yx = yxb + i*16;
        float gg = gp[yx*128];
        float sa = sp[yx*128];
        float z  = (gg - mu) * rstd * gam + bet;
        float sc = 1.f / (1.f + expf(-z));
        float cn = (1.f + sc) * sa;
        sm4[d*SM4_STRIDE + yx] = cn;
        s += cn; ss += cn*cn;
    }
#pragma unroll
    for (int off = 16; off >= 1; off >>= 1) {
        s  += __shfl_xor_sync(0xffffffffu, s,  off);
        ss += __shfl_xor_sync(0xffffffffu, ss, off);
    }
    int wid = tid >> 5;
    if ((tid & 31) == 0) { sm4[RED + wid] = s; sm4[RED + 8 + wid] = ss; }
    __syncthreads();
    if (tid == 0) {
        float S = 0.f, Q = 0.f;
        for (int w = 0; w < 8; w++) { S += sm4[RED + w]; Q += sm4[RED + 8 + w]; }
        const float inv = 1.f / 16384.f;
        float m = S * inv;
        float var = Q * inv - m*m;
        sm4[RED + 16] = m;
        sm4[RED + 17] = rsqrtf(var + EPSV);
    }
    __syncthreads();
    float m = sm4[RED + 16], r = sm4[RED + 17];
    float* ob = out + ((o*32 + b) << 14);
    for (int i = 0; i < 64; i++) {
        int idx = i*256 + tid;
        float v = sm4[(idx >> 10)*SM4_STRIDE + (idx & 1023)];
        ob[idx] = (v - m) * r * ln_gamma[idx] + ln_beta[idx];
    }
}

// ---------------- launch ------------------------------------------------
extern "C" void kernel_launch(void* const* d_in, const int* in_sizes, int n_in,
                              void* d_out, int out_size) {
    const float* caps = (const float*)d_in[0];
    const float* Wt   = (const float*)d_in[1];
    const float* bt   = (const float*)d_in[2];
    const float* Wv   = (const float*)d_in[3];
    const float* bv   = (const float*)d_in[4];
    const float* Ws   = (const float*)d_in[5];
    const float* bng  = (const float*)d_in[6];
    const float* bnb  = (const float*)d_in[7];
    const float* lng  = (const float*)d_in[8];
    const float* lnb  = (const float*)d_in[9];
    float* out = (float*)d_out;

    const int smemA = 8192 + 64*225*4;            // 65792
    const int smem4 = (16*SM4_STRIDE + 32) * 4;
    cudaFuncSetAttribute(k_prepA, cudaFuncAttributeMaxDynamicSharedMemorySize, smemA);
    cudaFuncSetAttribute(k_final, cudaFuncAttributeMaxDynamicSharedMemorySize, smem4);

    k_prepB<<<1792, 256>>>(Wt);
    k_prepA<<<512, 256, smemA>>>(caps);
    k_gemm<<<dim3(8, 256), 256>>>(bt);
    k_route<<<NPTS/4, 256>>>(Wv, bv);
    k_gate<<<NPTS/8, 256>>>(Ws);
    k_bnstats<<<1, 256>>>();
    k_final<<<256, 256, smem4>>>(bng, bnb, lng, lnb, out);
}

// round 8
// speedup vs baseline: 1.1653x; 1.0444x over previous
#include <cuda_runtime.h>
#include <cuda_bf16.h>
#include <math.h>
#include <stdint.h>
#include <string.h>

// Problem constants
#define BATCH 32
#define CIN   8
#define COUT  8
#define KP    4
#define DIN   16
#define DOUT  16
#define SS_   32
#define EPSV  1e-5f

#define NPTS  (BATCH*SS_*SS_)      // 32768 spatial points (b,y,x)
#define NOC   (CIN*COUT*DOUT)      // 1024 conv output channels
#define KDIM  144                  // GEMM K (fp32)
#define KE2   288                  // [hi(144) | lo(144)] bf16 layout
#define OD    (COUT*DOUT)          // 128 (o,d) pairs per point

typedef unsigned long long u64;

// ---------------- packed f32x2 helpers ------------------------------------
__device__ __forceinline__ u64 pack2(float lo, float hi) {
    u64 d; asm("mov.b64 %0,{%1,%2};" : "=l"(d) : "f"(lo), "f"(hi)); return d;
}
__device__ __forceinline__ u64 ffma2(u64 a, u64 b, u64 c) {
    u64 d; asm("fma.rn.f32x2 %0,%1,%2,%3;" : "=l"(d) : "l"(a), "l"(b), "l"(c)); return d;
}
__device__ __forceinline__ u64 fadd2(u64 a, u64 b) {
    u64 d; asm("add.rn.f32x2 %0,%1,%2;" : "=l"(d) : "l"(a), "l"(b)); return d;
}
__device__ __forceinline__ void unpack2(u64 d, float& lo, float& hi) {
    asm("mov.b64 {%0,%1},%2;" : "=f"(lo), "=f"(hi) : "l"(d));
}

__device__ __forceinline__ uint32_t smem_u32(const void* p) {
    uint32_t a;
    asm("{ .reg .u64 t; cvta.to.shared.u64 t, %1; cvt.u32.u64 %0, t; }" : "=r"(a) : "l"(p));
    return a;
}
#define CP_ASYNC16(dst, src) asm volatile("cp.async.cg.shared.global [%0], [%1], 16;" :: "r"(dst), "l"(src))
#define CP_COMMIT()          asm volatile("cp.async.commit_group;" ::: "memory")

#define MMA16816(d, a0, a1, a2, a3, b0, b1) \
    asm volatile("mma.sync.aligned.m16n8k16.row.col.f32.bf16.bf16.f32 " \
        "{%0,%1,%2,%3},{%4,%5,%6,%7},{%8,%9},{%0,%1,%2,%3};" \
        : "+f"((d)[0]), "+f"((d)[1]), "+f"((d)[2]), "+f"((d)[3]) \
        : "r"(a0), "r"(a1), "r"(a2), "r"(a3), "r"(b0), "r"(b1))

// ---------------- scratch (device globals) --------------------------------
__device__ __align__(128) __nv_bfloat16 g_Ab[NPTS*KE2];    // im2col A [p][hi144|lo144]
__device__ __align__(128) __nv_bfloat16 g_Bb[NOC*KE2];     // weights  [oc][hi144|lo144]
__device__ __align__(128) float g_votes[NPTS*NOC];         // conv output [pt][oc]
__device__ __align__(128) float g_sumAtt[NPTS*OD];
__device__ __align__(128) float g_pmax[NPTS*OD];
__device__ __align__(128) float g_pmean[NPTS*OD];
__device__ __align__(128) float g_gate[NPTS*OD];
__device__ float g_psumArr[1024*8];
__device__ float g_pssArr[1024*8];
__device__ float g_bnMu[8];
__device__ float g_bnRstd[8];

// ---------------- kernel: prep B (split Wt -> bf16 [oc][288]) -------------
__global__ void k_prepB(const float* __restrict__ Wt) {
    int idx = blockIdx.x * 256 + threadIdx.x;   // 1152 blocks exact (294912)
    int oc = idx / KE2, e = idx % KE2;
    int t = e / KDIM, k = e - t*KDIM;
    float w = Wt[oc*KDIM + k];
    float hi = __bfloat162float(__float2bfloat16_rn(w));
    float v = t ? (w - hi) : hi;
    g_Bb[idx] = __float2bfloat16_rn(v);
}

// ---------------- kernel: prep A (im2col + split -> bf16 [p][288]) --------
// block = 64 points (2 y-rows of one image). grid 512.
__global__ __launch_bounds__(256) void k_prepA(const float* __restrict__ caps) {
    extern __shared__ char sm[];
    float* raw = (float*)sm;                       // 16 din x 4 rows x 32 = 2048 f
    uint32_t* outp = (uint32_t*)(sm + 8192);       // [64][145] u32 (padded stride)
    int tid = threadIdx.x;
    int m064 = blockIdx.x * 64;
    int b = m064 >> 10;
    int y0 = (m064 & 1023) >> 5;
    for (int i = tid; i < 2048; i += 256) {
        int din = i >> 7, rem = i & 127, yy = y0 - 1 + (rem >> 5), x = rem & 31;
        raw[i] = ((unsigned)yy < 32u) ? caps[b*16384 + din*1024 + yy*32 + x] : 0.f;
    }
    __syncthreads();
    int p = tid & 63, part = tid >> 6;
    int y_local = p >> 5, x = p & 31;
    bool isLo = part >= 2;
    int j0 = (part & 1) * 36;
    for (int j = j0; j < j0 + 36; j++) {
        float v[2];
#pragma unroll
        for (int q = 0; q < 2; q++) {
            int k = 2*j + q;
            int din = k / 9, r = k - din*9;
            int ry = r / 3;
            int xx = x + (r - ry*3) - 1;
            v[q] = ((unsigned)xx < 32u) ? raw[din*128 + (y_local + ry)*32 + xx] : 0.f;
        }
        uint32_t u;
        if (!isLo) {
            __nv_bfloat162 h2 = __float22bfloat162_rn(make_float2(v[0], v[1]));
            memcpy(&u, &h2, 4);
            outp[p*145 + j] = u;            // hi at u32 cols 0..71
        } else {
            float h0 = __bfloat162float(__float2bfloat16_rn(v[0]));
            float h1 = __bfloat162float(__float2bfloat16_rn(v[1]));
            __nv_bfloat162 l2 = __float22bfloat162_rn(make_float2(v[0]-h0, v[1]-h1));
            memcpy(&u, &l2, 4);
            outp[p*145 + 72 + j] = u;       // lo at u32 cols 72..143
        }
    }
    __syncthreads();
    uint32_t* gdst = (uint32_t*)((char*)g_Ab + (size_t)m064 * (KE2*2));
    for (int i = tid; i < 64*144; i += 256)
        gdst[i] = outp[(i/144)*145 + (i%144)];
}

// ---------------- kernel: bf16 mma.sync GEMM votes = A x B^T + bias -------
// BM=256, BN=128, 512 threads (4M x 4N warps, warp tile 64x32), K chunks of
// 16 with 3 MMAs/chunk (Ahi·Bhi + Ahi·Blo + Alo·Bhi), 3-stage cp.async.
#define STG 15360     // elems per stage: A 256x40 + B 128x40
__device__ __forceinline__ void gload(uint32_t dbase, const char* Asrc,
                                      const char* Bsrc, int c, int tid) {
#pragma unroll
    for (int i = 0; i < 2; i++) {
        int q = i*512 + tid;
        int row = q >> 2, part = q & 3;
        uint32_t dst = dbase + row*80 + ((part < 2) ? 0 : 32) + (part & 1)*16;
        CP_ASYNC16(dst, Asrc + (size_t)row*576 + ((part < 2) ? 0 : 288) + c*32 + (part & 1)*16);
    }
    {
        int row = tid >> 2, part = tid & 3;
        uint32_t dst = dbase + 20480 + row*80 + ((part < 2) ? 0 : 32) + (part & 1)*16;
        CP_ASYNC16(dst, Bsrc + (size_t)row*576 + ((part < 2) ? 0 : 288) + c*32 + (part & 1)*16);
    }
}

__global__ __launch_bounds__(512, 1) void k_gemm(const float* __restrict__ bt) {
    extern __shared__ __nv_bfloat16 gsm[];
    float* bias_s = (float*)(gsm + 3*STG);
    const int tid = threadIdx.x;
    const int lane = tid & 31;
    const int wid = tid >> 5;
    const int warpM = wid & 3;     // 4 M-warps (64 rows each)
    const int warpN = wid >> 2;    // 4 N-warps (32 cols each)
    const int n0 = blockIdx.x * 128;
    const int m0 = blockIdx.y * 256;
    if (tid < 128) bias_s[tid] = bt[n0 + tid];

    const char* Asrc = (const char*)g_Ab + (size_t)m0 * (KE2*2);
    const char* Bsrc = (const char*)g_Bb + (size_t)n0 * (KE2*2);
    const uint32_t sb = smem_u32(gsm);

    gload(sb,           Asrc, Bsrc, 0, tid); CP_COMMIT();
    gload(sb + STG*2,   Asrc, Bsrc, 1, tid); CP_COMMIT();

    float acc[4][4][4];
#pragma unroll
    for (int a = 0; a < 4; a++)
#pragma unroll
        for (int b = 0; b < 4; b++)
#pragma unroll
            for (int c = 0; c < 4; c++) acc[a][b][c] = 0.f;

    const int qr = lane >> 2;
    const int qc = lane & 3;
    const int cb = qc*2;

    for (int c = 0; c < 9; c++) {
        if (c == 8) asm volatile("cp.async.wait_group 0;" ::: "memory");
        else        asm volatile("cp.async.wait_group 1;" ::: "memory");
        __syncthreads();
        if (c + 2 < 9) {
            gload(sb + ((c+2)%3)*STG*2, Asrc, Bsrc, c+2, tid);
            CP_COMMIT();
        }
        const __nv_bfloat16* Sa  = gsm + (c%3)*STG;
        const __nv_bfloat16* Sb2 = Sa + 10240;

        uint32_t ah[4][4], bh[4][2], bl[4][2];
#pragma unroll
        for (int mf = 0; mf < 4; mf++) {
            int r = warpM*64 + mf*16 + qr;
            ah[mf][0] = *(const uint32_t*)&Sa[r*40 + cb];
            ah[mf][1] = *(const uint32_t*)&Sa[(r+8)*40 + cb];
            ah[mf][2] = *(const uint32_t*)&Sa[r*40 + cb + 8];
            ah[mf][3] = *(const uint32_t*)&Sa[(r+8)*40 + cb + 8];
        }
#pragma unroll
        for (int nf = 0; nf < 4; nf++) {
            int n = warpN*32 + nf*8 + qr;
            bh[nf][0] = *(const uint32_t*)&Sb2[n*40 + cb];
            bh[nf][1] = *(const uint32_t*)&Sb2[n*40 + cb + 8];
            bl[nf][0] = *(const uint32_t*)&Sb2[n*40 + cb + 16];
            bl[nf][1] = *(const uint32_t*)&Sb2[n*40 + cb + 24];
        }
#pragma unroll
        for (int mf = 0; mf < 4; mf++)
#pragma unroll
            for (int nf = 0; nf < 4; nf++) {
                MMA16816(acc[mf][nf], ah[mf][0], ah[mf][1], ah[mf][2], ah[mf][3],
                         bh[nf][0], bh[nf][1]);
                MMA16816(acc[mf][nf], ah[mf][0], ah[mf][1], ah[mf][2], ah[mf][3],
                         bl[nf][0], bl[nf][1]);
            }
#pragma unroll
        for (int mf = 0; mf < 4; mf++) {
            int r = warpM*64 + mf*16 + qr;
            uint32_t al0 = *(const uint32_t*)&Sa[r*40 + cb + 16];
            uint32_t al1 = *(const uint32_t*)&Sa[(r+8)*40 + cb + 16];
            uint32_t al2 = *(const uint32_t*)&Sa[r*40 + cb + 24];
            uint32_t al3 = *(const uint32_t*)&Sa[(r+8)*40 + cb + 24];
#pragma unroll
            for (int nf = 0; nf < 4; nf++)
                MMA16816(acc[mf][nf], al0, al1, al2, al3, bh[nf][0], bh[nf][1]);
        }
    }

    // epilogue: + bias, direct stores
#pragma unroll
    for (int mf = 0; mf < 4; mf++) {
        int row0 = m0 + warpM*64 + mf*16 + qr;
#pragma unroll
        for (int nf = 0; nf < 4; nf++) {
            int cl = warpN*32 + nf*8 + qc*2;
            float b0 = bias_s[cl], b1 = bias_s[cl + 1];
            float2 o0 = make_float2(acc[mf][nf][0] + b0, acc[mf][nf][1] + b1);
            float2 o1 = make_float2(acc[mf][nf][2] + b0, acc[mf][nf][3] + b1);
            *(float2*)(g_votes + (size_t)row0*1024 + n0 + cl) = o0;
            *(float2*)(g_votes + (size_t)(row0+8)*1024 + n0 + cl) = o1;
        }
    }
}

// ---------------- kernel 2: values + pooling + agreement routing ----------
// 64 threads per point; each thread owns one (o, d-pair).
// softmax weights via w_c = 1/std_c (min-std stabilizer cancels).
__global__ __launch_bounds__(256) void k_route(const float* __restrict__ Wv,
                                               const float* __restrict__ bv) {
    __shared__ __align__(16) float wv_s[2048];
    __shared__ float bv_s[256];
    int tid = threadIdx.x;
    for (int i = tid; i < 2048; i += 256) wv_s[i] = Wv[i];
    if (tid < 256) bv_s[tid] = bv[tid];
    __syncthreads();

    int pt  = blockIdx.x * 4 + (tid >> 6);
    int l64 = tid & 63;
    int o   = l64 >> 3;
    const float* vp = g_votes + (size_t)pt * 1024 + l64 * 2;

    u64 vt2[8];
#pragma unroll
    for (int c = 0; c < 8; c++)
        vt2[c] = *(const u64*)(vp + c*128);

    float av[2] = {0.f, 0.f};
    float wsum[2] = {0.f, 0.f};
    float pmax[2] = {-1e30f, -1e30f};
    u64 psum2 = 0ULL;

    const float4* wv4 = (const float4*)wv_s;
#pragma unroll
    for (int c2 = 0; c2 < 8; c2++) {
        u64 ks = 0ULL, kq = 0ULL;
#pragma unroll
        for (int kp = 0; kp < 4; kp++) {
            int m = kp*8 + c2;
            float4 wa = wv4[(o*32 + m)*2 + 0];
            float4 wb = wv4[(o*32 + m)*2 + 1];
            float bvv = bv_s[o*32 + m];
            u64 v0 = pack2(bvv, bvv), w;
            w = pack2(wa.x, wa.x); v0 = ffma2(w, vt2[0], v0);
            w = pack2(wa.y, wa.y); v0 = ffma2(w, vt2[1], v0);
            w = pack2(wa.z, wa.z); v0 = ffma2(w, vt2[2], v0);
            w = pack2(wa.w, wa.w); v0 = ffma2(w, vt2[3], v0);
            w = pack2(wb.x, wb.x); v0 = ffma2(w, vt2[4], v0);
            w = pack2(wb.y, wb.y); v0 = ffma2(w, vt2[5], v0);
            w = pack2(wb.z, wb.z); v0 = ffma2(w, vt2[6], v0);
            w = pack2(wb.w, wb.w); v0 = ffma2(w, vt2[7], v0);
            ks = fadd2(ks, v0);
            kq = ffma2(v0, v0, kq);
            psum2 = fadd2(psum2, v0);
            float f0, f1;
            unpack2(v0, f0, f1);
            pmax[0] = fmaxf(pmax[0], f0);
            pmax[1] = fmaxf(pmax[1], f1);
        }
        float ksf0, ksf1, kqf0, kqf1;
        unpack2(ks, ksf0, ksf1);
        unpack2(kq, kqf0, kqf1);
        {
            float mu  = ksf0 * 0.25f;
            float var = fmaxf(kqf0 * 0.25f - mu*mu, 1e-30f);
            float rs  = rsqrtf(var);
            av[0] += mu * rs; wsum[0] += rs;
        }
        {
            float mu  = ksf1 * 0.25f;
            float var = fmaxf(kqf1 * 0.25f - mu*mu, 1e-30f);
            float rs  = rsqrtf(var);
            av[1] += mu * rs; wsum[1] += rs;
        }
    }

    float pf0, pf1;
    unpack2(psum2, pf0, pf1);
    size_t off = (size_t)pt*128 + l64*2;
    *(float2*)(g_sumAtt + off) = make_float2(av[0]/wsum[0], av[1]/wsum[1]);
    *(float2*)(g_pmax   + off) = make_float2(pmax[0], pmax[1]);
    *(float2*)(g_pmean  + off) = make_float2(pf0 * (1.f/32.f), pf1 * (1.f/32.f));
}

// ---------------- kernel 3: 3D gate conv (3x3x3, pad1) + BN partials -----
// (reverted to the proven R5 layout: thread = (pt, o), 16 d in registers)
__global__ __launch_bounds__(256) void k_gate(const float* __restrict__ Ws) {
    __shared__ float ws_s[54];
    __shared__ float bsum[8], bss[8];
    int tid = threadIdx.x;
    if (tid < 54) ws_s[tid] = Ws[tid];
    if (tid < 8) { bsum[tid] = 0.f; bss[tid] = 0.f; }
    __syncthreads();

    int pt = blockIdx.x * 32 + (tid >> 3);
    int o  = tid & 7;
    int b  = pt >> 10, yx = pt & 1023;
    int y  = yx >> 5,  x  = yx & 31;

    float acc[16];
#pragma unroll
    for (int d = 0; d < 16; d++) acc[d] = 0.f;

    for (int dy = -1; dy <= 1; dy++) {
        int yy = y + dy;
        if ((unsigned)yy >= 32u) continue;
        for (int dx = -1; dx <= 1; dx++) {
            int xx = x + dx;
            if ((unsigned)xx >= 32u) continue;
            int base = ((b << 10) + (yy << 5) + xx)*128 + (o << 4);
            const float4* pm = (const float4*)(g_pmax  + base);
            const float4* pn = (const float4*)(g_pmean + base);
            float rmx[16], rmn[16];
#pragma unroll
            for (int q = 0; q < 4; q++) {
                float4 a = pm[q]; float4 c = pn[q];
                rmx[q*4+0] = a.x; rmx[q*4+1] = a.y; rmx[q*4+2] = a.z; rmx[q*4+3] = a.w;
                rmn[q*4+0] = c.x; rmn[q*4+1] = c.y; rmn[q*4+2] = c.z; rmn[q*4+3] = c.w;
            }
            int wo = (dy+1)*3 + (dx+1);
#pragma unroll
            for (int kz = 0; kz < 3; kz++) {
                float wm = ws_s[kz*9 + wo];
                float wn = ws_s[27 + kz*9 + wo];
#pragma unroll
                for (int d = 0; d < 16; d++) {
                    int s = d + kz - 1;
                    if (s >= 0 && s < 16) acc[d] += wm*rmx[s] + wn*rmn[s];
                }
            }
        }
    }
    float* gp = g_gate + pt*128 + (o << 4);
#pragma unroll
    for (int q = 0; q < 4; q++)
        *(float4*)(gp + q*4) = make_float4(acc[q*4+0], acc[q*4+1], acc[q*4+2], acc[q*4+3]);

    float s1 = 0.f, s2 = 0.f;
#pragma unroll
    for (int d = 0; d < 16; d++) { s1 += acc[d]; s2 += acc[d]*acc[d]; }
    s1 += __shfl_xor_sync(0xffffffffu, s1, 8);
    s2 += __shfl_xor_sync(0xffffffffu, s2, 8);
    s1 += __shfl_xor_sync(0xffffffffu, s1, 16);
    s2 += __shfl_xor_sync(0xffffffffu, s2, 16);
    if ((tid & 31) < 8) { atomicAdd(&bsum[o], s1); atomicAdd(&bss[o], s2); }
    __syncthreads();
    if (tid < 8) {
        g_psumArr[blockIdx.x*8 + tid] = bsum[tid];
        g_pssArr [blockIdx.x*8 + tid] = bss[tid];
    }
}

// ---------------- kernel 3b: BN stats finalize (1024 partials) ------------
__global__ void k_bnstats() {
    __shared__ float ss1[256], ss2[256];
    int tid = threadIdx.x;
    int o = tid & 7, seg = tid >> 3;
    float a = 0.f, c = 0.f;
    for (int i = seg*32; i < seg*32 + 32; i++) {
        a += g_psumArr[i*8 + o];
        c += g_pssArr [i*8 + o];
    }
    ss1[tid] = a; ss2[tid] = c;
    __syncthreads();
    if (tid < 8) {
        float A = 0.f, C = 0.f;
        for (int s = 0; s < 32; s++) { A += ss1[s*8 + tid]; C += ss2[s*8 + tid]; }
        const float inv = 1.f / 524288.f;
        float mu = A * inv;
        float var = C * inv - mu*mu;
        g_bnMu[tid]   = mu;
        g_bnRstd[tid] = rsqrtf(var + EPSV);
    }
}

// ---------------- kernel 4: gate apply + LayerNorm + transpose out -------
#define SM4_STRIDE 1025
__global__ __launch_bounds__(256) void k_final(const float* __restrict__ bn_gamma,
                                               const float* __restrict__ bn_beta,
                                               const float* __restrict__ ln_gamma,
                                               const float* __restrict__ ln_beta,
                                               float* __restrict__ out) {
    extern __shared__ float sm4[];
    const int RED = 16*SM4_STRIDE;
    int tid = threadIdx.x;
    int b = blockIdx.x & 31;
    int o = blockIdx.x >> 5;
    float mu = g_bnMu[o], rstd = g_bnRstd[o];
    float gam = bn_gamma[0], bet = bn_beta[0];

    int d   = tid & 15;
    int yxb = tid >> 4;
    const float* gp = g_gate   + (b << 10)*128 + (o << 4) + d;
    const float* sp = g_sumAtt + (b << 10)*128 + (o << 4) + d;
    float s = 0.f, ss = 0.f;
    for (int i = 0; i < 64; i++) {
        int yx = yxb + i*16;
        float gg = gp[yx*128];
        float sa = sp[yx*128];
        float z  = (gg - mu) * rstd * gam + bet;
        float sc = 1.f / (1.f + expf(-z));
        float cn = (1.f + sc) * sa;
        sm4[d*SM4_STRIDE + yx] = cn;
        s += cn; ss += cn*cn;
    }
#pragma unroll
    for (int off = 16; off >= 1; off >>= 1) {
        s  += __shfl_xor_sync(0xffffffffu, s,  off);
        ss += __shfl_xor_sync(0xffffffffu, ss, off);
    }
    int wid = tid >> 5;
    if ((tid & 31) == 0) { sm4[RED + wid] = s; sm4[RED + 8 + wid] = ss; }
    __syncthreads();
    if (tid == 0) {
        float S = 0.f, Q = 0.f;
        for (int w = 0; w < 8; w++) { S += sm4[RED + w]; Q += sm4[RED + 8 + w]; }
        const float inv = 1.f / 16384.f;
        float m = S * inv;
        float var = Q * inv - m*m;
        sm4[RED + 16] = m;
        sm4[RED + 17] = rsqrtf(var + EPSV);
    }
    __syncthreads();
    float m = sm4[RED + 16], r = sm4[RED + 17];
    float* ob = out + ((o*32 + b) << 14);
    for (int i = 0; i < 64; i++) {
        int idx = i*256 + tid;
        float v = sm4[(idx >> 10)*SM4_STRIDE + (idx & 1023)];
        ob[idx] = (v - m) * r * ln_gamma[idx] + ln_beta[idx];
    }
}

// ---------------- launch ------------------------------------------------
extern "C" void kernel_launch(void* const* d_in, const int* in_sizes, int n_in,
                              void* d_out, int out_size) {
    const float* caps = (const float*)d_in[0];
    const float* Wt   = (const float*)d_in[1];
    const float* bt   = (const float*)d_in[2];
    const float* Wv   = (const float*)d_in[3];
    const float* bv   = (const float*)d_in[4];
    const float* Ws   = (const float*)d_in[5];
    const float* bng  = (const float*)d_in[6];
    const float* bnb  = (const float*)d_in[7];
    const float* lng  = (const float*)d_in[8];
    const float* lnb  = (const float*)d_in[9];
    float* out = (float*)d_out;

    const int smemA = 8192 + 64*145*4;            // 45312
    const int smemG = 3*STG*2 + 512;              // 92672
    const int smem4 = (16*SM4_STRIDE + 32) * 4;
    cudaFuncSetAttribute(k_prepA, cudaFuncAttributeMaxDynamicSharedMemorySize, smemA);
    cudaFuncSetAttribute(k_gemm,  cudaFuncAttributeMaxDynamicSharedMemorySize, smemG);
    cudaFuncSetAttribute(k_final, cudaFuncAttributeMaxDynamicSharedMemorySize, smem4);

    k_prepB<<<1152, 256>>>(Wt);
    k_prepA<<<512, 256, smemA>>>(caps);
    k_gemm<<<dim3(8, 128), 512, smemG>>>(bt);
    k_route<<<NPTS/4, 256>>>(Wv, bv);
    k_gate<<<NPTS/32, 256>>>(Ws);
    k_bnstats<<<1, 256>>>();
    k_final<<<256, 256, smem4>>>(bng, bnb, lng, lnb, out);
}